// round 5
// baseline (speedup 1.0000x reference)
#include <cuda_runtime.h>

// Soft-PQ: out[n, m*128+d] = sum_k softmax_k(-(dist)/T) * C[m][k][d]
// logit_k = (2*<x_nm, c_mk> - |c_mk|^2) / T   (x^2 term cancels in softmax)
//
// Block: 64 rows x 1 subspace. 256 threads. 8x8 register tile per thread,
// accumulators packed as f32x2 and updated with fma.rn.f32x2 (2 FMA/issue).
// Reconstruction is sparse: weights < 1e-7 dropped (error <= 2.6e-5 rel).

#define TILE_N 64
#define KCW 256          // codewords per subspace
#define DM 128           // dims per subspace
#define KC 32            // d-chunk for the distance GEMM
#define LS 260           // logit smem row stride (floats): 16B-aligned rows, conflict-free scans
#define XS_STRIDE 36     // X tile row stride (floats)

#define SM_X 0
#define SM_C (TILE_N * XS_STRIDE)          // 2304 floats
#define SM_C2 (TILE_N * LS)                // 16640 floats (c2 array after logits)
#define SMEM_FLOATS (TILE_N * LS + KCW)    // 16896 floats
#define SMEM_BYTES (SMEM_FLOATS * 4)       // 67584 bytes

__device__ __forceinline__ unsigned long long ffma2(unsigned long long a,
                                                    unsigned long long b,
                                                    unsigned long long c) {
    unsigned long long d;
    asm("fma.rn.f32x2 %0, %1, %2, %3;" : "=l"(d) : "l"(a), "l"(b), "l"(c));
    return d;
}

__device__ __forceinline__ unsigned long long pack2(float lo, float hi) {
    unsigned long long d;
    asm("mov.b64 %0, {%1, %2};" : "=l"(d) : "f"(lo), "f"(hi));
    return d;
}

__device__ __forceinline__ float2 unpack2(unsigned long long v) {
    float2 r;
    asm("mov.b64 {%0, %1}, %2;" : "=f"(r.x), "=f"(r.y) : "l"(v));
    return r;
}

__global__ void __launch_bounds__(256, 2)
softpq_kernel(const float* __restrict__ x,
              const float* __restrict__ cb,
              const void* __restrict__ tptr,
              float* __restrict__ out,
              int N)
{
    extern __shared__ float sm[];
    float* Xs  = sm + SM_X;     // [64][36]  (row-major, padded)
    float* Cs  = sm + SM_C;     // [32][256] (d-major, k contiguous)
    float* Ls  = sm;            // [64][260] logits (union with Xs/Cs, used after GEMM)
    float* c2s = sm + SM_C2;    // [256]

    const int tid  = threadIdx.x;
    const int tx   = tid & 31;   // col group: cols tx*8 .. tx*8+7
    const int ty   = tid >> 5;   // row group: rows ty*8 .. ty*8+7
    const int m    = blockIdx.y;
    const int row0 = blockIdx.x * TILE_N;

    // ---- temperature: robust to int32 / float32 scalar encodings ----
    float temp;
    {
        float tf = *(const float*)tptr;
        if (tf >= 1e-6f && tf <= 1e6f) {
            temp = tf;
        } else {
            int ti = *(const int*)tptr;
            temp = (ti != 0) ? (float)ti : 1.0f;
        }
    }
    const float inv_temp = 1.0f / temp;

    const float* Cm = cb + (size_t)m * (KCW * DM);

    unsigned long long acc2[8][4];
#pragma unroll
    for (int i = 0; i < 8; ++i)
#pragma unroll
        for (int j = 0; j < 4; ++j) acc2[i][j] = 0ull;

    float c2 = 0.0f;

    // ================= distance GEMM: logits = 2*X·Cᵀ (per d-chunk) =================
    for (int ch = 0; ch < DM / KC; ++ch) {
        // load X tile: 64 rows x 32 d (coalesced 128B per row)
#pragma unroll
        for (int it = 0; it < 2; ++it) {
            int f = tid + it * 256;
            int r = f >> 3, q = f & 7;
            int gr = row0 + r;
            float4 v = make_float4(0.f, 0.f, 0.f, 0.f);
            if (gr < N)
                v = *(const float4*)(x + (size_t)gr * 1024 + m * DM + ch * KC + q * 4);
            *(float4*)(Xs + r * XS_STRIDE + q * 4) = v;
        }
        // load+transpose C chunk: warp ty owns k = ty*32+tx; conflict-free STS (bank = k%32)
        {
            int k = ty * 32 + tx;
            const float* cg = Cm + (size_t)k * DM + ch * KC;
#pragma unroll
            for (int q = 0; q < 8; ++q) {
                float4 v = *(const float4*)(cg + q * 4);
                Cs[(q * 4 + 0) * KCW + k] = v.x;
                Cs[(q * 4 + 1) * KCW + k] = v.y;
                Cs[(q * 4 + 2) * KCW + k] = v.z;
                Cs[(q * 4 + 3) * KCW + k] = v.w;
            }
        }
        __syncthreads();

        // c2 partial for codeword tid (conflict-free: bank = tid%32)
#pragma unroll 8
        for (int d = 0; d < KC; ++d) {
            float v = Cs[d * KCW + tid];
            c2 = fmaf(v, v, c2);
        }

        // register-tile GEMM, f32x2-packed accumulators
#pragma unroll 4
        for (int d4 = 0; d4 < KC; d4 += 4) {
#pragma unroll
            for (int e = 0; e < 4; ++e) {
                const float4* brow = (const float4*)(Cs + (d4 + e) * KCW);
                float4 b0 = brow[tx * 2];
                float4 b1 = brow[tx * 2 + 1];
                unsigned long long b2[4];
                b2[0] = pack2(b0.x, b0.y);
                b2[1] = pack2(b0.z, b0.w);
                b2[2] = pack2(b1.x, b1.y);
                b2[3] = pack2(b1.z, b1.w);
#pragma unroll
                for (int i = 0; i < 8; ++i) {
                    float av = Xs[(ty * 8 + i) * XS_STRIDE + d4 + e];
                    unsigned long long a2 = pack2(av, av);
#pragma unroll
                    for (int j = 0; j < 4; ++j)
                        acc2[i][j] = ffma2(a2, b2[j], acc2[i][j]);
                }
            }
        }
        __syncthreads();
    }

    // ================= write logits to smem =================
    c2s[tid] = c2;
    __syncthreads();

    const float two_it = 2.0f * inv_temp;
    {
        int colb = tx * 8;
        float cc[8];
#pragma unroll
        for (int j = 0; j < 8; ++j) cc[j] = c2s[colb + j] * inv_temp;
#pragma unroll
        for (int i = 0; i < 8; ++i) {
            int r = ty * 8 + i;
            float l[8];
#pragma unroll
            for (int j2 = 0; j2 < 4; ++j2) {
                float2 v = unpack2(acc2[i][j2]);
                l[j2 * 2 + 0] = fmaf(two_it, v.x, -cc[j2 * 2 + 0]);
                l[j2 * 2 + 1] = fmaf(two_it, v.y, -cc[j2 * 2 + 1]);
            }
            float* dst = Ls + r * LS + colb;
            *(float4*)(dst)     = make_float4(l[0], l[1], l[2], l[3]);
            *(float4*)(dst + 4) = make_float4(l[4], l[5], l[6], l[7]);
        }
    }
    __syncthreads();

    // ================= softmax (4 threads per row) + sparse reconstruction =================
    const int qi  = tid & 3;       // quad lane: owns k in [qi*64, qi*64+64) and dims [qi*32, qi*32+32)
    const int row = tid >> 2;      // 0..63
    float* Lrow = Ls + row * LS;
    const int kb = qi * 64;

    float mx = -3.402823466e38f;
#pragma unroll 8
    for (int t = 0; t < 64; ++t) mx = fmaxf(mx, Lrow[kb + t]);
    mx = fmaxf(mx, __shfl_xor_sync(0xffffffffu, mx, 1));
    mx = fmaxf(mx, __shfl_xor_sync(0xffffffffu, mx, 2));

    float s = 0.0f;
#pragma unroll 8
    for (int t = 0; t < 64; ++t) {
        float e = __expf(Lrow[kb + t] - mx);
        Lrow[kb + t] = e;
        s += e;
    }
    s += __shfl_xor_sync(0xffffffffu, s, 1);
    s += __shfl_xor_sync(0xffffffffu, s, 2);
    __syncwarp();

    const float invs = 1.0f / s;
    const float thr  = 1e-7f * s;   // drop weights < 1e-7 (error <= 2.6e-5 rel)

    float o[32];
#pragma unroll
    for (int q = 0; q < 32; ++q) o[q] = 0.0f;

    const float* Cq = Cm + qi * 32;
    for (int k = 0; k < KCW; ++k) {
        float e = Lrow[k];
        if (e > thr) {
            float p = e * invs;
            const float4* cp = (const float4*)(Cq + (size_t)k * DM);
#pragma unroll
            for (int q = 0; q < 8; ++q) {
                float4 c = cp[q];
                o[q * 4 + 0] = fmaf(p, c.x, o[q * 4 + 0]);
                o[q * 4 + 1] = fmaf(p, c.y, o[q * 4 + 1]);
                o[q * 4 + 2] = fmaf(p, c.z, o[q * 4 + 2]);
                o[q * 4 + 3] = fmaf(p, c.w, o[q * 4 + 3]);
            }
        }
    }

    int gr = row0 + row;
    if (gr < N) {
        float* op = out + (size_t)gr * 1024 + m * DM + qi * 32;
#pragma unroll
        for (int q = 0; q < 8; ++q)
            ((float4*)op)[q] = make_float4(o[q * 4], o[q * 4 + 1], o[q * 4 + 2], o[q * 4 + 3]);
    }
}

extern "C" void kernel_launch(void* const* d_in, const int* in_sizes, int n_in,
                              void* d_out, int out_size)
{
    const float* x  = (const float*)d_in[0];
    const float* cb = (const float*)d_in[1];
    const void*  t  = d_in[2];
    float* out = (float*)d_out;

    int N = in_sizes[0] / 1024;   // D = M*D_M = 1024

    cudaFuncSetAttribute(softpq_kernel,
                         cudaFuncAttributeMaxDynamicSharedMemorySize, SMEM_BYTES);

    dim3 grid((N + TILE_N - 1) / TILE_N, 8);
    softpq_kernel<<<grid, 256, SMEM_BYTES>>>(x, cb, t, out, N);
}

// round 6
// speedup vs baseline: 1.1254x; 1.1254x over previous
#include <cuda_runtime.h>

// Soft-PQ: out[n, m*128+d] = sum_k softmax_k(-(dist)/T) * C[m][k][d]
// logit_k = (2*<x_nm, c_mk> - |c_mk|^2) / T   (x^2 term cancels in softmax)
//
// Block: 64 rows x 1 subspace. 256 threads. 8x8 register tile per thread,
// f32x2-packed accumulators (fma.rn.f32x2 = 2 FMA/issue).
// R6: L1-wavefront fixes — contiguous warp-wide B LDS.128 (cols tx*4 / 128+tx*4),
// d-vectorized broadcast A loads, natural f32x2 register pairing for B,
// float4 softmax/recon scans.

#define TILE_N 64
#define KCW 256          // codewords per subspace
#define DM 128           // dims per subspace
#define KC 32            // d-chunk for the distance GEMM
#define LS 260           // logit smem row stride (floats)
#define XS_STRIDE 36     // X tile row stride (floats)

#define SM_X 0
#define SM_C (TILE_N * XS_STRIDE)          // 2304 floats
#define SM_C2 (TILE_N * LS)                // 16640 floats
#define SMEM_FLOATS (TILE_N * LS + KCW)    // 16896 floats
#define SMEM_BYTES (SMEM_FLOATS * 4)       // 67584 bytes

__device__ __forceinline__ unsigned long long ffma2(unsigned long long a,
                                                    unsigned long long b,
                                                    unsigned long long c) {
    unsigned long long d;
    asm("fma.rn.f32x2 %0, %1, %2, %3;" : "=l"(d) : "l"(a), "l"(b), "l"(c));
    return d;
}

__device__ __forceinline__ unsigned long long pack2(float lo, float hi) {
    unsigned long long d;
    asm("mov.b64 %0, {%1, %2};" : "=l"(d) : "f"(lo), "f"(hi));
    return d;
}

__device__ __forceinline__ float2 unpack2(unsigned long long v) {
    float2 r;
    asm("mov.b64 {%0, %1}, %2;" : "=f"(r.x), "=f"(r.y) : "l"(v));
    return r;
}

__global__ void __launch_bounds__(256, 2)
softpq_kernel(const float* __restrict__ x,
              const float* __restrict__ cb,
              const void* __restrict__ tptr,
              float* __restrict__ out,
              int N)
{
    extern __shared__ float sm[];
    float* Xs  = sm + SM_X;     // [64][36]
    float* Cs  = sm + SM_C;     // [32][256] (d-major, k contiguous)
    float* Ls  = sm;            // [64][260] logits (union, used after GEMM)
    float* c2s = sm + SM_C2;    // [256]

    const int tid  = threadIdx.x;
    const int tx   = tid & 31;   // cols tx*4..tx*4+3 and 128+tx*4..+3
    const int ty   = tid >> 5;   // rows ty*8..ty*8+7
    const int m    = blockIdx.y;
    const int row0 = blockIdx.x * TILE_N;

    // ---- temperature: robust to int32 / float32 scalar encodings ----
    float temp;
    {
        float tf = *(const float*)tptr;
        if (tf >= 1e-6f && tf <= 1e6f) {
            temp = tf;
        } else {
            int ti = *(const int*)tptr;
            temp = (ti != 0) ? (float)ti : 1.0f;
        }
    }
    const float inv_temp = 1.0f / temp;

    const float* Cm = cb + (size_t)m * (KCW * DM);

    unsigned long long acc2[8][4];
#pragma unroll
    for (int i = 0; i < 8; ++i)
#pragma unroll
        for (int j = 0; j < 4; ++j) acc2[i][j] = 0ull;

    float c2 = 0.0f;

    // ================= distance GEMM: 2*X·Cᵀ (per d-chunk) =================
    for (int ch = 0; ch < DM / KC; ++ch) {
        // load X tile: 64 rows x 32 d (coalesced 128B per row)
#pragma unroll
        for (int it = 0; it < 2; ++it) {
            int f = tid + it * 256;
            int r = f >> 3, q = f & 7;
            int gr = row0 + r;
            float4 v = make_float4(0.f, 0.f, 0.f, 0.f);
            if (gr < N)
                v = *(const float4*)(x + (size_t)gr * 1024 + m * DM + ch * KC + q * 4);
            *(float4*)(Xs + r * XS_STRIDE + q * 4) = v;
        }
        // load+transpose C chunk: warp ty owns k = ty*32+tx (conflict-free STS)
        {
            int k = ty * 32 + tx;
            const float* cg = Cm + (size_t)k * DM + ch * KC;
#pragma unroll
            for (int q = 0; q < 8; ++q) {
                float4 v = *(const float4*)(cg + q * 4);
                Cs[(q * 4 + 0) * KCW + k] = v.x;
                Cs[(q * 4 + 1) * KCW + k] = v.y;
                Cs[(q * 4 + 2) * KCW + k] = v.z;
                Cs[(q * 4 + 3) * KCW + k] = v.w;
            }
        }
        __syncthreads();

        // c2 partial for codeword tid (bank = tid%32, conflict-free)
#pragma unroll 8
        for (int d = 0; d < KC; ++d) {
            float v = Cs[d * KCW + tid];
            c2 = fmaf(v, v, c2);
        }

        // register-tile GEMM: A d-vectorized broadcasts, B contiguous LDS.128
#pragma unroll
        for (int d4 = 0; d4 < KC; d4 += 4) {
            float4 a4[8];
#pragma unroll
            for (int i = 0; i < 8; ++i)
                a4[i] = *(const float4*)(Xs + (ty * 8 + i) * XS_STRIDE + d4);
#pragma unroll
            for (int e = 0; e < 4; ++e) {
                const float* brow = Cs + (d4 + e) * KCW;
                float4 b0 = *(const float4*)(brow + tx * 4);         // warp: 512B contiguous
                float4 b1 = *(const float4*)(brow + 128 + tx * 4);   // warp: 512B contiguous
                unsigned long long b2[4];
                b2[0] = pack2(b0.x, b0.y);
                b2[1] = pack2(b0.z, b0.w);
                b2[2] = pack2(b1.x, b1.y);
                b2[3] = pack2(b1.z, b1.w);
#pragma unroll
                for (int i = 0; i < 8; ++i) {
                    float av = ((const float*)&a4[i])[e];
                    unsigned long long av2 = pack2(av, av);
#pragma unroll
                    for (int j = 0; j < 4; ++j)
                        acc2[i][j] = ffma2(av2, b2[j], acc2[i][j]);
                }
            }
        }
        __syncthreads();
    }

    // ================= logits to smem =================
    c2s[tid] = c2;
    __syncthreads();

    const float two_it = 2.0f * inv_temp;
    {
        const int cA = tx * 4;
        const int cB = 128 + tx * 4;
        float cc[8];
#pragma unroll
        for (int j = 0; j < 4; ++j) cc[j]     = c2s[cA + j] * inv_temp;
#pragma unroll
        for (int j = 0; j < 4; ++j) cc[4 + j] = c2s[cB + j] * inv_temp;
#pragma unroll
        for (int i = 0; i < 8; ++i) {
            int r = ty * 8 + i;
            float l[8];
#pragma unroll
            for (int j2 = 0; j2 < 4; ++j2) {
                float2 v = unpack2(acc2[i][j2]);
                l[j2 * 2 + 0] = fmaf(two_it, v.x, -cc[j2 * 2 + 0]);
                l[j2 * 2 + 1] = fmaf(two_it, v.y, -cc[j2 * 2 + 1]);
            }
            float* dst = Ls + r * LS;
            *(float4*)(dst + cA) = make_float4(l[0], l[1], l[2], l[3]);
            *(float4*)(dst + cB) = make_float4(l[4], l[5], l[6], l[7]);
        }
    }
    __syncthreads();

    // ================= softmax (4 threads/row) + sparse reconstruction =================
    const int qi  = tid & 3;       // owns k in [qi*64, qi*64+64), dims [qi*32, qi*32+32)
    const int row = tid >> 2;
    float* Lrow = Ls + row * LS;
    float4* L4  = (float4*)(Lrow + qi * 64);

    float mx = -3.402823466e38f;
#pragma unroll
    for (int t = 0; t < 16; ++t) {
        float4 v = L4[t];
        mx = fmaxf(mx, fmaxf(fmaxf(v.x, v.y), fmaxf(v.z, v.w)));
    }
    mx = fmaxf(mx, __shfl_xor_sync(0xffffffffu, mx, 1));
    mx = fmaxf(mx, __shfl_xor_sync(0xffffffffu, mx, 2));

    float s = 0.0f;
#pragma unroll
    for (int t = 0; t < 16; ++t) {
        float4 v = L4[t];
        v.x = __expf(v.x - mx);
        v.y = __expf(v.y - mx);
        v.z = __expf(v.z - mx);
        v.w = __expf(v.w - mx);
        s += (v.x + v.y) + (v.z + v.w);
        L4[t] = v;
    }
    s += __shfl_xor_sync(0xffffffffu, s, 1);
    s += __shfl_xor_sync(0xffffffffu, s, 2);
    __syncwarp();

    const float invs = 1.0f / s;
    const float thr  = 1e-7f * s;   // drop weights < 1e-7 (error <= 2.6e-5 rel)

    float o[32];
#pragma unroll
    for (int q = 0; q < 32; ++q) o[q] = 0.0f;

    const float* Cq = Cm + qi * 32;
    for (int k4 = 0; k4 < KCW; k4 += 4) {
        float4 e4 = *(const float4*)(Lrow + k4);
#pragma unroll
        for (int u = 0; u < 4; ++u) {
            float e = ((const float*)&e4)[u];
            if (e > thr) {
                float p = e * invs;
                const float4* cp = (const float4*)(Cq + (size_t)(k4 + u) * DM);
#pragma unroll
                for (int q = 0; q < 8; ++q) {
                    float4 c = cp[q];
                    o[q * 4 + 0] = fmaf(p, c.x, o[q * 4 + 0]);
                    o[q * 4 + 1] = fmaf(p, c.y, o[q * 4 + 1]);
                    o[q * 4 + 2] = fmaf(p, c.z, o[q * 4 + 2]);
                    o[q * 4 + 3] = fmaf(p, c.w, o[q * 4 + 3]);
                }
            }
        }
    }

    int gr = row0 + row;
    if (gr < N) {
        float* op = out + (size_t)gr * 1024 + m * DM + qi * 32;
#pragma unroll
        for (int q = 0; q < 8; ++q)
            ((float4*)op)[q] = make_float4(o[q * 4], o[q * 4 + 1], o[q * 4 + 2], o[q * 4 + 3]);
    }
}

extern "C" void kernel_launch(void* const* d_in, const int* in_sizes, int n_in,
                              void* d_out, int out_size)
{
    const float* x  = (const float*)d_in[0];
    const float* cb = (const float*)d_in[1];
    const void*  t  = d_in[2];
    float* out = (float*)d_out;

    int N = in_sizes[0] / 1024;   // D = M*D_M = 1024

    cudaFuncSetAttribute(softpq_kernel,
                         cudaFuncAttributeMaxDynamicSharedMemorySize, SMEM_BYTES);

    dim3 grid((N + TILE_N - 1) / TILE_N, 8);
    softpq_kernel<<<grid, 256, SMEM_BYTES>>>(x, cb, t, out, N);
}

// round 8
// speedup vs baseline: 1.3662x; 1.2140x over previous
#include <cuda_runtime.h>
#include <cuda_bf16.h>

// Soft-PQ via warp-level HMMA (mma.sync m16n8k16 bf16), hi/lo 3-MMA fp32 emulation.
// (tcgen05 is unusable: harness assembles at .target sm_103, no 'a' features.)
// logit_k = (2*<x,c_k> - |c_k|^2)/T  (x^2 cancels in softmax).
// CTA = 64 rows x 1 subspace, 256 threads. Warp grid 2x4: warp = 32 rows x 64 cols.
// B fragments pre-baked to exact HMMA thread layout by prep kernel (hi+lo images).
// Sparse reconstruction with logit cutoff (p < 1e-7 dropped, err <= 2.6e-5 rel).

#define KCW 256
#define DM  128
#define TILE_M 64

// ---- smem byte offsets ----
#define OFF_BH  0         // 65536: B frag image (hi)
#define OFF_BL  65536     // 65536: B frag image (lo)
#define OFF_XH  131072    // 17408: X stage hi (64 rows x 272B)
#define OFF_XL  148480    // 17408: X stage lo
#define OFF_C2  165888    // 1024:  c2 * invT (256 f)
#define OFF_STM 166912    // 1024:  max partials [wc*64+row]
#define OFF_STS 167936    // 1024:  sum partials
#define SMEM_TOTAL 168960
#define XSTRIDE 272       // bytes per staged X row (136 bf16; 68 words -> conflict-free)
#define LSTRIDE 264       // floats per logit row (reuses B region after sync)

__device__ __align__(16) uint2 g_bfH[8][8192];   // [m][((nt*8)+kt)*32+lane]
__device__ __align__(16) uint2 g_bfL[8][8192];
__device__ float g_c2[8 * KCW];

__device__ __forceinline__ void mma_bf16(float* d, const unsigned* a, uint2 b) {
    asm volatile(
        "mma.sync.aligned.m16n8k16.row.col.f32.bf16.bf16.f32 "
        "{%0,%1,%2,%3}, {%4,%5,%6,%7}, {%8,%9}, {%0,%1,%2,%3};"
        : "+f"(d[0]), "+f"(d[1]), "+f"(d[2]), "+f"(d[3])
        : "r"(a[0]), "r"(a[1]), "r"(a[2]), "r"(a[3]), "r"(b.x), "r"(b.y));
}

// ======================= prep kernel =======================
// Bakes codebook into hi/lo bf16 HMMA B-fragment images + c2.
// Fragment (m16n8k16 col-major B): lane q=lane%4, g=lane/4; n = nt*8+g;
// reg.x = {k=kt*16+q*2, +1}, reg.y = {k=kt*16+q*2+8, +9}.
__global__ void prep_kernel(const float* __restrict__ cb) {
    int m = blockIdx.x, tid = threadIdx.x;
    // c2
    if (tid < KCW) {
        const float* src = cb + ((size_t)m * KCW + tid) * DM;
        float c2 = 0.0f;
        for (int d4 = 0; d4 < DM; d4 += 4) {
            float4 v = *(const float4*)(src + d4);
            c2 = fmaf(v.x, v.x, c2); c2 = fmaf(v.y, v.y, c2);
            c2 = fmaf(v.z, v.z, c2); c2 = fmaf(v.w, v.w, c2);
        }
        g_c2[m * KCW + tid] = c2;
    }
    // fragments: 8192 entries, 256 threads x 32
    for (int e = tid; e < 8192; e += 256) {
        int lane = e & 31, kt = (e >> 5) & 7, nt = e >> 8;
        int q = lane & 3, g = lane >> 2;
        int n = nt * 8 + g;
        int k0 = kt * 16 + q * 2;
        const float* src = cb + ((size_t)m * KCW + n) * DM;
        float f[4] = { src[k0], src[k0 + 1], src[k0 + 8], src[k0 + 9] };
        unsigned h[4], l[4];
#pragma unroll
        for (int u = 0; u < 4; ++u) {
            __nv_bfloat16 hb = __float2bfloat16_rn(f[u]);
            __nv_bfloat16 lb = __float2bfloat16_rn(f[u] - __bfloat162float(hb));
            h[u] = __bfloat16_as_ushort(hb);
            l[u] = __bfloat16_as_ushort(lb);
        }
        g_bfH[m][e] = make_uint2(h[0] | (h[1] << 16), h[2] | (h[3] << 16));
        g_bfL[m][e] = make_uint2(l[0] | (l[1] << 16), l[2] | (l[3] << 16));
    }
}

// ======================= main kernel =======================
__global__ void __launch_bounds__(256, 1)
softpq_hmma_kernel(const float* __restrict__ x,
                   const float* __restrict__ cb,
                   const void* __restrict__ tptr,
                   float* __restrict__ out,
                   int N)
{
    extern __shared__ char smem[];
    const int tid  = threadIdx.x;
    const int wid  = tid >> 5;
    const int lane = tid & 31;
    const int q    = lane & 3;
    const int g    = lane >> 2;
    const int wr   = wid & 1;    // row group: rows wr*32 .. wr*32+31
    const int wc   = wid >> 1;   // col group: cols wc*64 .. wc*64+63
    const int m    = blockIdx.y;
    const int row0 = blockIdx.x * TILE_M;

    // temperature (robust to int32/float32 scalar encodings)
    float temp;
    {
        float tf = *(const float*)tptr;
        if (tf >= 1e-6f && tf <= 1e6f) temp = tf;
        else { int ti = *(const int*)tptr; temp = (ti != 0) ? (float)ti : 1.0f; }
    }
    const float inv_temp = 1.0f / temp;
    const float two_it = 2.0f * inv_temp;

    // --- B fragment images: linear copy (L2-hot, 1MB total working set) ---
    {
        const uint4* sh = (const uint4*)g_bfH[m];
        const uint4* sl = (const uint4*)g_bfL[m];
        uint4* dh = (uint4*)(smem + OFF_BH);
        uint4* dl = (uint4*)(smem + OFF_BL);
#pragma unroll
        for (int i = 0; i < 16; ++i) {
            int idx = tid + i * 256;
            dh[idx] = sh[idx];
            dl[idx] = sl[idx];
        }
    }

    // --- X tile: coalesced load, hi/lo bf16 split, stage (272B row stride) ---
    {
#pragma unroll
        for (int it = 0; it < 8; ++it) {
            int f = tid + it * 256;           // float4 index
            int r = f >> 5, c4 = f & 31;      // whole warp on one row
            int gr = row0 + r;
            float4 v = make_float4(0.f, 0.f, 0.f, 0.f);
            if (gr < N)
                v = *(const float4*)(x + (size_t)gr * 1024 + m * DM + c4 * 4);
            float fv[4] = { v.x, v.y, v.z, v.w };
            unsigned h[4], l[4];
#pragma unroll
            for (int u = 0; u < 4; ++u) {
                __nv_bfloat16 hb = __float2bfloat16_rn(fv[u]);
                __nv_bfloat16 lb = __float2bfloat16_rn(fv[u] - __bfloat162float(hb));
                h[u] = __bfloat16_as_ushort(hb);
                l[u] = __bfloat16_as_ushort(lb);
            }
            *(uint2*)(smem + OFF_XH + r * XSTRIDE + c4 * 8) =
                make_uint2(h[0] | (h[1] << 16), h[2] | (h[3] << 16));
            *(uint2*)(smem + OFF_XL + r * XSTRIDE + c4 * 8) =
                make_uint2(l[0] | (l[1] << 16), l[2] | (l[3] << 16));
        }
    }

    // --- c2 * invT ---
    ((float*)(smem + OFF_C2))[tid] = g_c2[m * KCW + tid] * inv_temp;
    __syncthreads();

    // --- 3-pass HMMA GEMM: acc = <x,c> in fp32 ---
    float acc[2][8][4];
#pragma unroll
    for (int mt = 0; mt < 2; ++mt)
#pragma unroll
        for (int j = 0; j < 8; ++j)
#pragma unroll
            for (int u = 0; u < 4; ++u) acc[mt][j][u] = 0.0f;

    const char* const aB[3] = { smem + OFF_XH, smem + OFF_XH, smem + OFF_XL };
    const char* const bB[3] = { smem + OFF_BH, smem + OFF_BL, smem + OFF_BH };

#pragma unroll
    for (int pass = 0; pass < 3; ++pass) {
        const char* Ab = aB[pass] + (wr * 32 + g) * XSTRIDE + q * 4;
        const char* Bb = bB[pass] + wc * 16384 + lane * 8;
#pragma unroll
        for (int kt = 0; kt < 8; ++kt) {
            unsigned a[2][4];
#pragma unroll
            for (int mt = 0; mt < 2; ++mt) {
                const char* ap = Ab + mt * (16 * XSTRIDE) + kt * 32;
                a[mt][0] = *(const unsigned*)(ap);
                a[mt][1] = *(const unsigned*)(ap + 8 * XSTRIDE);
                a[mt][2] = *(const unsigned*)(ap + 16);
                a[mt][3] = *(const unsigned*)(ap + 8 * XSTRIDE + 16);
            }
#pragma unroll
            for (int j = 0; j < 8; ++j) {
                uint2 b = *(const uint2*)(Bb + (j * 8 + kt) * 256);
                mma_bf16(acc[0][j], a[0], b);
                mma_bf16(acc[1][j], a[1], b);
            }
        }
    }

    // --- logits in registers + per-row online stats ---
    {
        const float* c2s = (const float*)(smem + OFF_C2);
        float c2v[8][2];
#pragma unroll
        for (int j = 0; j < 8; ++j) {
            int col = wc * 64 + j * 8 + q * 2;
            c2v[j][0] = c2s[col];
            c2v[j][1] = c2s[col + 1];
        }
#pragma unroll
        for (int mt = 0; mt < 2; ++mt)
#pragma unroll
            for (int j = 0; j < 8; ++j) {
                acc[mt][j][0] = fmaf(acc[mt][j][0], two_it, -c2v[j][0]);
                acc[mt][j][1] = fmaf(acc[mt][j][1], two_it, -c2v[j][1]);
                acc[mt][j][2] = fmaf(acc[mt][j][2], two_it, -c2v[j][0]);
                acc[mt][j][3] = fmaf(acc[mt][j][3], two_it, -c2v[j][1]);
            }

        float mx[2][2], sm_[2][2];
#pragma unroll
        for (int mt = 0; mt < 2; ++mt)
#pragma unroll
            for (int rh = 0; rh < 2; ++rh) {
                float mv = -3.402823466e38f;
#pragma unroll
                for (int j = 0; j < 8; ++j) {
                    mv = fmaxf(mv, acc[mt][j][rh * 2 + 0]);
                    mv = fmaxf(mv, acc[mt][j][rh * 2 + 1]);
                }
                mv = fmaxf(mv, __shfl_xor_sync(0xffffffffu, mv, 1));
                mv = fmaxf(mv, __shfl_xor_sync(0xffffffffu, mv, 2));
                float sv = 0.0f;
#pragma unroll
                for (int j = 0; j < 8; ++j) {
                    sv += __expf(acc[mt][j][rh * 2 + 0] - mv);
                    sv += __expf(acc[mt][j][rh * 2 + 1] - mv);
                }
                sv += __shfl_xor_sync(0xffffffffu, sv, 1);
                sv += __shfl_xor_sync(0xffffffffu, sv, 2);
                mx[mt][rh] = mv;
                sm_[mt][rh] = sv;
            }

        __syncthreads();   // all warps done with B region -> safe to write logits

        float* Ls  = (float*)smem;
        float* stm = (float*)(smem + OFF_STM);
        float* sts = (float*)(smem + OFF_STS);
#pragma unroll
        for (int mt = 0; mt < 2; ++mt)
#pragma unroll
            for (int rh = 0; rh < 2; ++rh) {
                int row = wr * 32 + mt * 16 + rh * 8 + g;
#pragma unroll
                for (int j = 0; j < 8; ++j) {
                    int col = wc * 64 + j * 8 + q * 2;
                    *(float2*)(Ls + row * LSTRIDE + col) =
                        make_float2(acc[mt][j][rh * 2 + 0], acc[mt][j][rh * 2 + 1]);
                }
                if (q == 0) {
                    stm[wc * 64 + row] = mx[mt][rh];
                    sts[wc * 64 + row] = sm_[mt][rh];
                }
            }
    }
    __syncthreads();

    // --- sparse reconstruction (4 threads / row, dims qi*32..qi*32+31) ---
    {
        const float* Ls  = (const float*)smem;
        const float* stm = (const float*)(smem + OFF_STM);
        const float* sts = (const float*)(smem + OFF_STS);
        const int row = tid >> 2, qi = tid & 3;

        float M = stm[row];
#pragma unroll
        for (int w = 1; w < 4; ++w) M = fmaxf(M, stm[w * 64 + row]);
        float S = 0.0f;
#pragma unroll
        for (int w = 0; w < 4; ++w) S += sts[w * 64 + row] * __expf(stm[w * 64 + row] - M);
        const float invS = 1.0f / S;
        const float lthr = M + __logf(1e-7f * S);   // p < 1e-7 dropped

        float o[32];
#pragma unroll
        for (int u = 0; u < 32; ++u) o[u] = 0.0f;

        const float* Lrow = Ls + row * LSTRIDE;
        const float* Cq = cb + (size_t)m * KCW * DM + qi * 32;
        for (int k4 = 0; k4 < KCW; k4 += 4) {
            float4 l4 = *(const float4*)(Lrow + k4);
            float lv[4] = { l4.x, l4.y, l4.z, l4.w };
#pragma unroll
            for (int u = 0; u < 4; ++u) {
                if (lv[u] > lthr) {
                    float p = __expf(lv[u] - M) * invS;
                    const float4* cp = (const float4*)(Cq + (size_t)(k4 + u) * DM);
#pragma unroll
                    for (int e = 0; e < 8; ++e) {
                        float4 c = cp[e];
                        o[e * 4 + 0] = fmaf(p, c.x, o[e * 4 + 0]);
                        o[e * 4 + 1] = fmaf(p, c.y, o[e * 4 + 1]);
                        o[e * 4 + 2] = fmaf(p, c.z, o[e * 4 + 2]);
                        o[e * 4 + 3] = fmaf(p, c.w, o[e * 4 + 3]);
                    }
                }
            }
        }

        int gr = row0 + row;
        if (gr < N) {
            float4* op = (float4*)(out + (size_t)gr * 1024 + m * DM + qi * 32);
#pragma unroll
            for (int e = 0; e < 8; ++e)
                op[e] = make_float4(o[e * 4], o[e * 4 + 1], o[e * 4 + 2], o[e * 4 + 3]);
        }
    }
}

extern "C" void kernel_launch(void* const* d_in, const int* in_sizes, int n_in,
                              void* d_out, int out_size)
{
    const float* x  = (const float*)d_in[0];
    const float* cb = (const float*)d_in[1];
    const void*  t  = d_in[2];
    float* out = (float*)d_out;

    int N = in_sizes[0] / 1024;   // D = M*D_M = 1024

    prep_kernel<<<8, 256>>>(cb);

    cudaFuncSetAttribute(softpq_hmma_kernel,
                         cudaFuncAttributeMaxDynamicSharedMemorySize, SMEM_TOTAL);
    dim3 grid((N + TILE_M - 1) / TILE_M, 8);
    softpq_hmma_kernel<<<grid, 256, SMEM_TOTAL>>>(x, cb, t, out, N);
}